// round 8
// baseline (speedup 1.0000x reference)
#include <cuda_runtime.h>
#include <cuda_fp16.h>
#include <math_constants.h>

#define NN 50000
#define EE 800000
#define FIN 128
#define HF 256      // HEADS*HID = 4*64
#define GG 256
#define CC 10

typedef unsigned long long ull;

// ---------------- scratch (no allocations allowed) ----------------
__device__ __half g_Whh[(size_t)NN * HF];   // Wh in fp16 (gather source)
__device__ float g_out1[(size_t)NN * HF];
__device__ float g_out2[(size_t)NN * HF];
__device__ float g_ls[NN * 4];
__device__ float g_ld[NN * 4];
__device__ int   g_deg[NN];
__device__ int   g_rowptr[NN + 1];
__device__ int   g_cursor[NN];
__device__ int   g_srcs[EE];
__device__ float g_mx[GG * HF];
__device__ float g_sm[GG * HF];
__device__ int   g_cnt[GG];

__device__ __forceinline__ float lrelu(float v) { return v > 0.f ? v : 0.01f * v; }

__device__ __forceinline__ ull pack2(float lo, float hi) {
    ull r;
    asm("mov.b64 %0, {%1, %2};" : "=l"(r) : "f"(lo), "f"(hi));
    return r;
}
__device__ __forceinline__ void unpack2(ull v, float& lo, float& hi) {
    asm("mov.b64 {%0, %1}, %2;" : "=f"(lo), "=f"(hi) : "l"(v));
}
__device__ __forceinline__ void ffma2(ull& acc, ull a, ull b) {
    asm("fma.rn.f32x2 %0, %1, %2, %0;" : "+l"(acc) : "l"(a), "l"(b));
}
__device__ __forceinline__ unsigned f16x2_of(float lo, float hi) {
    unsigned r;
    asm("cvt.rn.f16x2.f32 %0, %1, %2;" : "=r"(r) : "f"(hi), "f"(lo));  // first src -> high half
    return r;
}
__device__ __forceinline__ float2 h2f(unsigned u) {
    __half2 h = *reinterpret_cast<__half2*>(&u);
    return __half22float2(h);
}

// ---------------- init ----------------
__global__ void init_kernel() {
    int i = blockIdx.x * blockDim.x + threadIdx.x;
    if (i < NN) g_deg[i] = 0;
    if (i < GG * HF) { g_mx[i] = -CUDART_INF_F; g_sm[i] = 0.f; }
    if (i < GG) g_cnt[i] = 0;
}

// ---------------- CSR build ----------------
__global__ void count_kernel(const int* __restrict__ ei) {
    int e = blockIdx.x * blockDim.x + threadIdx.x;
    if (e >= EE) return;
    atomicAdd(&g_deg[ei[EE + e]], 1);
}

__global__ void scan_kernel() {
    const int T = 1024;
    int tid = threadIdx.x;
    int per = (NN + T - 1) / T;
    int start = tid * per;
    int end = start + per; if (end > NN) end = NN; if (start > NN) start = NN;
    int s = 0;
    for (int i = start; i < end; i++) s += g_deg[i];
    __shared__ int sums[T];
    sums[tid] = s;
    __syncthreads();
    for (int off = 1; off < T; off <<= 1) {
        int v = (tid >= off) ? sums[tid - off] : 0;
        __syncthreads();
        sums[tid] += v;
        __syncthreads();
    }
    int run = (tid > 0) ? sums[tid - 1] : 0;
    for (int i = start; i < end; i++) {
        g_rowptr[i] = run;
        g_cursor[i] = run;
        run += g_deg[i];
    }
    if (tid == T - 1) g_rowptr[NN] = run;
}

__global__ void scatter_kernel(const int* __restrict__ ei) {
    int e = blockIdx.x * blockDim.x + threadIdx.x;
    if (e >= EE) return;
    int dst = ei[EE + e];
    int pos = atomicAdd(&g_cursor[dst], 1);
    g_srcs[pos] = ei[e];
}

// ---- GEMM + fused logits: Whh[M,256] = fp16(A[M,K]*B[K,256]); one head/block ----
// f32x2 math, 8x4 per-thread tile, 32-warp occupancy target.
template <int K>
__global__ __launch_bounds__(256, 4)
void gemm_fused_kernel(const float* __restrict__ A, const float* __restrict__ B,
                       __half* __restrict__ Whh,
                       const float* __restrict__ a_src, const float* __restrict__ a_dst,
                       int M) {
    constexpr int BM = 128, BN = 64, BK = 16;
    __shared__ ulonglong2 As2[BK / 2][BM];          // (a_k,a_k,a_k1,a_k1), 16KB
    __shared__ __align__(16) float Bs[BK][BN];      // 4KB
    __shared__ float s_as[BN], s_ad[BN];
    int tid = threadIdx.x;
    int tx = tid & 15, ty = tid >> 4;
    int m0 = blockIdx.y * BM, n0 = blockIdx.x * BN;   // n0 = head*64
    if (tid < BN) { s_as[tid] = a_src[n0 + tid]; s_ad[tid] = a_dst[n0 + tid]; }

    ull acc2[8][2];
#pragma unroll
    for (int i = 0; i < 8; i++) { acc2[i][0] = 0ull; acc2[i][1] = 0ull; }

    float4 aR[2], bR;
    // prefetch tile 0
#pragma unroll
    for (int u = 0; u < 2; u++) {
        int t = tid + u * 256;
        int m = t >> 2, c = (t & 3) * 4;
        int gm = m0 + m;
        aR[u] = (gm < M) ? *(const float4*)&A[(size_t)gm * K + c]
                         : make_float4(0.f, 0.f, 0.f, 0.f);
    }
    bR = *(const float4*)&B[(size_t)(tid >> 4) * 256 + n0 + (tid & 15) * 4];

    for (int k0 = 0; k0 < K; k0 += BK) {
#pragma unroll
        for (int u = 0; u < 2; u++) {
            int t = tid + u * 256;
            int m = t >> 2, c = (t & 3) * 4;     // c in {0,4,8,12}
            As2[(c >> 1) + 0][m] = make_ulonglong2(pack2(aR[u].x, aR[u].x), pack2(aR[u].y, aR[u].y));
            As2[(c >> 1) + 1][m] = make_ulonglong2(pack2(aR[u].z, aR[u].z), pack2(aR[u].w, aR[u].w));
        }
        *(float4*)&Bs[tid >> 4][(tid & 15) * 4] = bR;
        __syncthreads();
        int kn = k0 + BK;
        if (kn < K) {
#pragma unroll
            for (int u = 0; u < 2; u++) {
                int t = tid + u * 256;
                int m = t >> 2, c = (t & 3) * 4;
                int gm = m0 + m;
                aR[u] = (gm < M) ? *(const float4*)&A[(size_t)gm * K + kn + c]
                                 : make_float4(0.f, 0.f, 0.f, 0.f);
            }
            bR = *(const float4*)&B[(size_t)(kn + (tid >> 4)) * 256 + n0 + (tid & 15) * 4];
        }
#pragma unroll
        for (int kk = 0; kk < BK / 2; kk++) {
            ulonglong2 q = *(const ulonglong2*)&Bs[2 * kk][tx * 4];
            ulonglong2 r = *(const ulonglong2*)&Bs[2 * kk + 1][tx * 4];
#pragma unroll
            for (int i = 0; i < 8; i++) {
                ulonglong2 a = As2[kk][ty * 8 + i];
                ffma2(acc2[i][0], a.x, q.x);
                ffma2(acc2[i][1], a.x, q.y);
                ffma2(acc2[i][0], a.y, r.x);
                ffma2(acc2[i][1], a.y, r.y);
            }
        }
        __syncthreads();
    }

    int h = blockIdx.x;  // head
#pragma unroll
    for (int i = 0; i < 8; i++) {
        int gm = m0 + ty * 8 + i;
        float c0, c1, c2, c3;
        unpack2(acc2[i][0], c0, c1);
        unpack2(acc2[i][1], c2, c3);
        if (gm < M) {
            unsigned p0 = f16x2_of(c0, c1);
            unsigned p1 = f16x2_of(c2, c3);
            *(uint2*)&Whh[(size_t)gm * 256 + n0 + tx * 4] = make_uint2(p0, p1);
        }
        int f = tx * 4;
        float ls = c0 * s_as[f] + c1 * s_as[f + 1] + c2 * s_as[f + 2] + c3 * s_as[f + 3];
        float ld = c0 * s_ad[f] + c1 * s_ad[f + 1] + c2 * s_ad[f + 2] + c3 * s_ad[f + 3];
#pragma unroll
        for (int off = 8; off >= 1; off >>= 1) {
            ls += __shfl_xor_sync(0xffffffffu, ls, off);
            ld += __shfl_xor_sync(0xffffffffu, ld, off);
        }
        if (tx == 0 && gm < M) {
            g_ls[gm * 4 + h] = ls;
            g_ld[gm * 4 + h] = ld;
        }
    }
}

// ---- fused edge-softmax + aggregation + ELU (warp per dst, fp16 gather) ----
__device__ __forceinline__ void acc_edge(float* acc, float ph, uint4 w) {
    float2 f0 = h2f(w.x), f1 = h2f(w.y), f2 = h2f(w.z), f3 = h2f(w.w);
    acc[0] = fmaf(ph, f0.x, acc[0]); acc[1] = fmaf(ph, f0.y, acc[1]);
    acc[2] = fmaf(ph, f1.x, acc[2]); acc[3] = fmaf(ph, f1.y, acc[3]);
    acc[4] = fmaf(ph, f2.x, acc[4]); acc[5] = fmaf(ph, f2.y, acc[5]);
    acc[6] = fmaf(ph, f3.x, acc[6]); acc[7] = fmaf(ph, f3.y, acc[7]);
}

__global__ __launch_bounds__(256)
void agg_kernel(const __half* __restrict__ Whh, float* __restrict__ out) {
    int warp = (blockIdx.x * blockDim.x + threadIdx.x) >> 5;
    int lane = threadIdx.x & 31;
    if (warp >= NN) return;
    int n = warp;
    int start = g_rowptr[n], end = g_rowptr[n + 1];
    float4 dn = *(const float4*)(g_ld + n * 4);

    float acc[8];
#pragma unroll
    for (int j = 0; j < 8; j++) acc[j] = 0.f;
    float z0 = 0.f, z1 = 0.f, z2 = 0.f, z3 = 0.f;
    int hsel = lane >> 3;

    int i = start;
    for (; i + 3 < end; i += 4) {
        int s0 = g_srcs[i], s1 = g_srcs[i + 1], s2 = g_srcs[i + 2], s3 = g_srcs[i + 3];
        float4 l0 = *(const float4*)(g_ls + s0 * 4);
        float4 l1 = *(const float4*)(g_ls + s1 * 4);
        float4 l2 = *(const float4*)(g_ls + s2 * 4);
        float4 l3 = *(const float4*)(g_ls + s3 * 4);
        uint4 w0 = *(const uint4*)(Whh + (size_t)s0 * HF + lane * 8);
        uint4 w1 = *(const uint4*)(Whh + (size_t)s1 * HF + lane * 8);
        uint4 w2 = *(const uint4*)(Whh + (size_t)s2 * HF + lane * 8);
        uint4 w3 = *(const uint4*)(Whh + (size_t)s3 * HF + lane * 8);

        float pa0 = __expf(lrelu(l0.x + dn.x)), pa1 = __expf(lrelu(l0.y + dn.y));
        float pa2 = __expf(lrelu(l0.z + dn.z)), pa3 = __expf(lrelu(l0.w + dn.w));
        float pb0 = __expf(lrelu(l1.x + dn.x)), pb1 = __expf(lrelu(l1.y + dn.y));
        float pb2 = __expf(lrelu(l1.z + dn.z)), pb3 = __expf(lrelu(l1.w + dn.w));
        float pc0 = __expf(lrelu(l2.x + dn.x)), pc1 = __expf(lrelu(l2.y + dn.y));
        float pc2 = __expf(lrelu(l2.z + dn.z)), pc3 = __expf(lrelu(l2.w + dn.w));
        float pd0 = __expf(lrelu(l3.x + dn.x)), pd1 = __expf(lrelu(l3.y + dn.y));
        float pd2 = __expf(lrelu(l3.z + dn.z)), pd3 = __expf(lrelu(l3.w + dn.w));
        z0 += pa0 + pb0 + pc0 + pd0;
        z1 += pa1 + pb1 + pc1 + pd1;
        z2 += pa2 + pb2 + pc2 + pd2;
        z3 += pa3 + pb3 + pc3 + pd3;
        float pha = (hsel == 0) ? pa0 : (hsel == 1) ? pa1 : (hsel == 2) ? pa2 : pa3;
        float phb = (hsel == 0) ? pb0 : (hsel == 1) ? pb1 : (hsel == 2) ? pb2 : pb3;
        float phc = (hsel == 0) ? pc0 : (hsel == 1) ? pc1 : (hsel == 2) ? pc2 : pc3;
        float phd = (hsel == 0) ? pd0 : (hsel == 1) ? pd1 : (hsel == 2) ? pd2 : pd3;
        acc_edge(acc, pha, w0);
        acc_edge(acc, phb, w1);
        acc_edge(acc, phc, w2);
        acc_edge(acc, phd, w3);
    }
    for (; i < end; i++) {
        int s = g_srcs[i];
        float4 l = *(const float4*)(g_ls + s * 4);
        uint4 w = *(const uint4*)(Whh + (size_t)s * HF + lane * 8);
        float p0 = __expf(lrelu(l.x + dn.x)), p1 = __expf(lrelu(l.y + dn.y));
        float p2 = __expf(lrelu(l.z + dn.z)), p3 = __expf(lrelu(l.w + dn.w));
        z0 += p0; z1 += p1; z2 += p2; z3 += p3;
        float ph = (hsel == 0) ? p0 : (hsel == 1) ? p1 : (hsel == 2) ? p2 : p3;
        acc_edge(acc, ph, w);
    }
    float zh = (hsel == 0) ? z0 : (hsel == 1) ? z1 : (hsel == 2) ? z2 : z3;
    float inv = 1.f / (zh + 1e-16f);
    float res[8];
#pragma unroll
    for (int j = 0; j < 8; j++) {
        float v = acc[j] * inv;
        res[j] = v > 0.f ? v : (__expf(v) - 1.f);  // ELU
    }
    float* o = out + (size_t)n * HF + lane * 8;
    *(float4*)o = make_float4(res[0], res[1], res[2], res[3]);
    *(float4*)(o + 4) = make_float4(res[4], res[5], res[6], res[7]);
}

// ---------------- segmented pooling (batch is sorted) ----------------
#define PN 128
__device__ __forceinline__ void pool_flush(int g, int f, float mx, float sm) {
    if (mx > -CUDART_INF_F) {
        int* amx = (int*)&g_mx[g * HF + f];
        if (mx >= 0.f) atomicMax(amx, __float_as_int(mx));
        else atomicMin((unsigned int*)amx, (unsigned int)__float_as_int(mx));
        atomicAdd(&g_sm[g * HF + f], sm);
    }
}
__global__ __launch_bounds__(256)
void pool_kernel(const float* __restrict__ x, const int* __restrict__ batch) {
    __shared__ int sb[PN];
    int b0 = blockIdx.x * PN;
    int cnt = NN - b0; if (cnt > PN) cnt = PN;
    for (int i = threadIdx.x; i < cnt; i += 256) sb[i] = batch[b0 + i];
    __syncthreads();
    int f = threadIdx.x;
    int g = sb[0];
    float mx = -CUDART_INF_F, sm = 0.f;
    int segc = 0;
    for (int i = 0; i < cnt; i++) {
        int gb = sb[i];
        if (gb != g) {
            pool_flush(g, f, mx, sm);
            if (f == 0) atomicAdd(&g_cnt[g], segc);
            g = gb; mx = -CUDART_INF_F; sm = 0.f; segc = 0;
        }
        float v = x[(size_t)(b0 + i) * HF + f];
        mx = fmaxf(mx, v); sm += v; segc++;
    }
    pool_flush(g, f, mx, sm);
    if (f == 0) atomicAdd(&g_cnt[g], segc);
}

// ---------------- finalize pool + linear ----------------
__global__ void final_kernel(const float* __restrict__ linW, const float* __restrict__ linb,
                             float* __restrict__ outp) {
    int t = blockIdx.x * blockDim.x + threadIdx.x;
    if (t >= GG * CC) return;
    int g = t / CC, c = t % CC;
    float cnt = fmaxf((float)g_cnt[g], 1.f);
    float inv = 1.f / cnt;
    float acc = linb[c];
    const float* mxr = g_mx + g * HF;
    const float* smr = g_sm + g * HF;
#pragma unroll 4
    for (int f = 0; f < HF; f++) {
        float mv = mxr[f];
        if (!isfinite(mv)) mv = 0.f;
        acc = fmaf(mv, linW[f * CC + c], acc);
    }
#pragma unroll 4
    for (int f = 0; f < HF; f++) {
        acc = fmaf(smr[f] * inv, linW[(HF + f) * CC + c], acc);
    }
    outp[t] = acc;
}

// ---------------- launch ----------------
extern "C" void kernel_launch(void* const* d_in, const int* in_sizes, int n_in,
                              void* d_out, int out_size) {
    const float* x      = (const float*)d_in[0];
    const int*   ei     = (const int*)d_in[1];
    const int*   batch  = (const int*)d_in[2];
    const float* W1     = (const float*)d_in[3];
    const float* a1s    = (const float*)d_in[4];
    const float* a1d    = (const float*)d_in[5];
    const float* W2     = (const float*)d_in[6];
    const float* a2s    = (const float*)d_in[7];
    const float* a2d    = (const float*)d_in[8];
    const float* linW   = (const float*)d_in[9];
    const float* linb   = (const float*)d_in[10];
    float* outp = (float*)d_out;

    __half* pWhh; cudaGetSymbolAddress((void**)&pWhh, g_Whh);
    float* pO1;  cudaGetSymbolAddress((void**)&pO1,  g_out1);
    float* pO2;  cudaGetSymbolAddress((void**)&pO2,  g_out2);

    dim3 g1(4, (NN + 127) / 128);
    int aggBlocks = (NN * 32 + 255) / 256;

    init_kernel<<<(GG * HF + 255) / 256, 256>>>();
    count_kernel<<<(EE + 255) / 256, 256>>>(ei);
    scan_kernel<<<1, 1024>>>();
    gemm_fused_kernel<FIN><<<g1, 256>>>(x, W1, pWhh, a1s, a1d, NN);   // profiled slot
    scatter_kernel<<<(EE + 255) / 256, 256>>>(ei);
    agg_kernel<<<aggBlocks, 256>>>(pWhh, pO1);

    gemm_fused_kernel<HF><<<g1, 256>>>(pO1, W2, pWhh, a2s, a2d, NN);
    agg_kernel<<<aggBlocks, 256>>>(pWhh, pO2);

    pool_kernel<<<(NN + PN - 1) / PN, 256>>>(pO2, batch);
    final_kernel<<<(GG * CC + 255) / 256, 256>>>(linW, linb, outp);
}

// round 9
// speedup vs baseline: 1.2795x; 1.2795x over previous
#include <cuda_runtime.h>
#include <cuda_fp16.h>
#include <math_constants.h>

#define NN 50000
#define EE 800000
#define FIN 128
#define HF 256      // HEADS*HID = 4*64
#define GG 256
#define CC 10

typedef unsigned long long ull;

// ---------------- scratch (no allocations allowed) ----------------
__device__ __half g_Whh[(size_t)NN * HF];   // Wh in fp16 (gather source)
__device__ float g_out1[(size_t)NN * HF];
__device__ float g_out2[(size_t)NN * HF];
__device__ float g_ls[NN * 4];
__device__ float g_ld[NN * 4];
__device__ int   g_deg[NN];
__device__ int   g_rowptr[NN + 1];
__device__ int   g_cursor[NN];
__device__ int   g_srcs[EE];
__device__ float g_mx[GG * HF];
__device__ float g_sm[GG * HF];
__device__ int   g_cnt[GG];

__device__ __forceinline__ float lrelu(float v) { return v > 0.f ? v : 0.01f * v; }

__device__ __forceinline__ ull pack2(float lo, float hi) {
    ull r;
    asm("mov.b64 %0, {%1, %2};" : "=l"(r) : "f"(lo), "f"(hi));
    return r;
}
__device__ __forceinline__ void unpack2(ull v, float& lo, float& hi) {
    asm("mov.b64 {%0, %1}, %2;" : "=f"(lo), "=f"(hi) : "l"(v));
}
__device__ __forceinline__ void ffma2(ull& acc, ull a, ull b) {
    asm("fma.rn.f32x2 %0, %1, %2, %0;" : "+l"(acc) : "l"(a), "l"(b));
}
__device__ __forceinline__ unsigned f16x2_of(float lo, float hi) {
    unsigned r;
    asm("cvt.rn.f16x2.f32 %0, %1, %2;" : "=r"(r) : "f"(hi), "f"(lo));  // first src -> high half
    return r;
}
__device__ __forceinline__ float2 h2f(unsigned u) {
    __half2 h = *reinterpret_cast<__half2*>(&u);
    return __half22float2(h);
}
__device__ __forceinline__ void cp16(void* smem_dst, const void* gsrc) {
    unsigned s = (unsigned)__cvta_generic_to_shared(smem_dst);
    asm volatile("cp.async.cg.shared.global [%0], [%1], 16;" :: "r"(s), "l"(gsrc));
}
__device__ __forceinline__ void cp_commit() { asm volatile("cp.async.commit_group;"); }
__device__ __forceinline__ void cp_wait1() { asm volatile("cp.async.wait_group 1;"); }
__device__ __forceinline__ void cp_wait0() { asm volatile("cp.async.wait_group 0;"); }

// ---------------- init ----------------
__global__ void init_kernel() {
    int i = blockIdx.x * blockDim.x + threadIdx.x;
    if (i < NN) g_deg[i] = 0;
    if (i < GG * HF) { g_mx[i] = -CUDART_INF_F; g_sm[i] = 0.f; }
    if (i < GG) g_cnt[i] = 0;
}

// ---------------- CSR build ----------------
__global__ void count_kernel(const int* __restrict__ ei) {
    int e = blockIdx.x * blockDim.x + threadIdx.x;
    if (e >= EE) return;
    atomicAdd(&g_deg[ei[EE + e]], 1);
}

__global__ void scan_kernel() {
    const int T = 1024;
    int tid = threadIdx.x;
    int per = (NN + T - 1) / T;
    int start = tid * per;
    int end = start + per; if (end > NN) end = NN; if (start > NN) start = NN;
    int s = 0;
    for (int i = start; i < end; i++) s += g_deg[i];
    __shared__ int sums[T];
    sums[tid] = s;
    __syncthreads();
    for (int off = 1; off < T; off <<= 1) {
        int v = (tid >= off) ? sums[tid - off] : 0;
        __syncthreads();
        sums[tid] += v;
        __syncthreads();
    }
    int run = (tid > 0) ? sums[tid - 1] : 0;
    for (int i = start; i < end; i++) {
        g_rowptr[i] = run;
        g_cursor[i] = run;
        run += g_deg[i];
    }
    if (tid == T - 1) g_rowptr[NN] = run;
}

__global__ void scatter_kernel(const int* __restrict__ ei) {
    int e = blockIdx.x * blockDim.x + threadIdx.x;
    if (e >= EE) return;
    int dst = ei[EE + e];
    int pos = atomicAdd(&g_cursor[dst], 1);
    g_srcs[pos] = ei[e];
}

// ---- GEMM + fused logits: Whh[M,256] = fp16(A[M,K]*B[K,256]) ----
// 8x8 f32x2 tile, cp.async 2-stage double buffer, plain A + register dup.
template <int K>
__global__ __launch_bounds__(256, 2)
void gemm_fused_kernel(const float* __restrict__ A, const float* __restrict__ B,
                       __half* __restrict__ Whh,
                       const float* __restrict__ a_src, const float* __restrict__ a_dst,
                       int M) {
    constexpr int BM = 128, BN = 128, BK = 16;
    constexpr int T = K / BK;                       // k-tiles: 8 or 16
    __shared__ __align__(16) float As[2][BM][BK];   // 8KB/stage
    __shared__ __align__(16) float Bs[2][BK][BN];   // 8KB/stage
    __shared__ float s_as[BN], s_ad[BN];
    int tid = threadIdx.x;
    int tx = tid & 15, ty = tid >> 4;
    int m0 = blockIdx.y * BM, n0 = blockIdx.x * BN;   // n0 in {0,128}
    if (tid < BN) { s_as[tid] = a_src[n0 + tid]; s_ad[tid] = a_dst[n0 + tid]; }

    ull acc2[8][4];
#pragma unroll
    for (int i = 0; i < 8; i++)
#pragma unroll
        for (int j = 0; j < 4; j++) acc2[i][j] = 0ull;

    // async-load one k-tile into stage st
    auto issue = [&](int st, int k0) {
#pragma unroll
        for (int u = 0; u < 2; u++) {
            int ch = tid + u * 256;                  // 0..511
            int m = ch >> 2, kq = (ch & 3) * 4;      // A: 128 rows x 4 chunks
            int gm = m0 + m; if (gm >= M) gm = M - 1;
            cp16(&As[st][m][kq], &A[(size_t)gm * K + k0 + kq]);
            int r = ch >> 5, cq = (ch & 31) * 4;     // B: 16 rows x 32 chunks
            cp16(&Bs[st][r][cq], &B[(size_t)(k0 + r) * 256 + n0 + cq]);
        }
        cp_commit();
    };

    issue(0, 0);

#pragma unroll 1
    for (int t = 0; t < T; t++) {
        int st = t & 1;
        if (t + 1 < T) { issue(st ^ 1, (t + 1) * BK); cp_wait1(); }
        else           { cp_wait0(); }
        __syncthreads();
#pragma unroll
        for (int kk = 0; kk < BK / 2; kk++) {
            ulonglong2 q0 = *(const ulonglong2*)&Bs[st][2 * kk][tx * 4];
            ulonglong2 q1 = *(const ulonglong2*)&Bs[st][2 * kk][64 + tx * 4];
            ulonglong2 r0 = *(const ulonglong2*)&Bs[st][2 * kk + 1][tx * 4];
            ulonglong2 r1 = *(const ulonglong2*)&Bs[st][2 * kk + 1][64 + tx * 4];
#pragma unroll
            for (int i = 0; i < 8; i++) {
                float2 ap = *(const float2*)&As[st][ty * 8 + i][2 * kk];
                ull a0 = pack2(ap.x, ap.x);
                ull a1 = pack2(ap.y, ap.y);
                ffma2(acc2[i][0], a0, q0.x);
                ffma2(acc2[i][1], a0, q0.y);
                ffma2(acc2[i][2], a0, q1.x);
                ffma2(acc2[i][3], a0, q1.y);
                ffma2(acc2[i][0], a1, r0.x);
                ffma2(acc2[i][1], a1, r0.y);
                ffma2(acc2[i][2], a1, r1.x);
                ffma2(acc2[i][3], a1, r1.y);
            }
        }
        __syncthreads();
    }

    int h0 = n0 >> 6;  // first head this block owns (0 or 2)
#pragma unroll
    for (int i = 0; i < 8; i++) {
        int gm = m0 + ty * 8 + i;
        float c0, c1, c2, c3, c4, c5, c6, c7;
        unpack2(acc2[i][0], c0, c1);
        unpack2(acc2[i][1], c2, c3);
        unpack2(acc2[i][2], c4, c5);
        unpack2(acc2[i][3], c6, c7);
        if (gm < M) {
            unsigned p0 = f16x2_of(c0, c1);
            unsigned p1 = f16x2_of(c2, c3);
            unsigned p2 = f16x2_of(c4, c5);
            unsigned p3 = f16x2_of(c6, c7);
            *(uint2*)&Whh[(size_t)gm * 256 + n0 + tx * 4] = make_uint2(p0, p1);
            *(uint2*)&Whh[(size_t)gm * 256 + n0 + 64 + tx * 4] = make_uint2(p2, p3);
        }
        int f = tx * 4;
        float lsA = c0 * s_as[f] + c1 * s_as[f + 1] + c2 * s_as[f + 2] + c3 * s_as[f + 3];
        float ldA = c0 * s_ad[f] + c1 * s_ad[f + 1] + c2 * s_ad[f + 2] + c3 * s_ad[f + 3];
        float lsB = c4 * s_as[64 + f] + c5 * s_as[64 + f + 1] + c6 * s_as[64 + f + 2] + c7 * s_as[64 + f + 3];
        float ldB = c4 * s_ad[64 + f] + c5 * s_ad[64 + f + 1] + c6 * s_ad[64 + f + 2] + c7 * s_ad[64 + f + 3];
#pragma unroll
        for (int off = 8; off >= 1; off >>= 1) {
            lsA += __shfl_xor_sync(0xffffffffu, lsA, off);
            ldA += __shfl_xor_sync(0xffffffffu, ldA, off);
            lsB += __shfl_xor_sync(0xffffffffu, lsB, off);
            ldB += __shfl_xor_sync(0xffffffffu, ldB, off);
        }
        if (tx == 0 && gm < M) {
            g_ls[gm * 4 + h0]     = lsA;
            g_ls[gm * 4 + h0 + 1] = lsB;
            g_ld[gm * 4 + h0]     = ldA;
            g_ld[gm * 4 + h0 + 1] = ldB;
        }
    }
}

// ---- fused edge-softmax + aggregation + ELU (warp per dst, fp16 gather) ----
__device__ __forceinline__ void acc_edge(float* acc, float ph, uint4 w) {
    float2 f0 = h2f(w.x), f1 = h2f(w.y), f2 = h2f(w.z), f3 = h2f(w.w);
    acc[0] = fmaf(ph, f0.x, acc[0]); acc[1] = fmaf(ph, f0.y, acc[1]);
    acc[2] = fmaf(ph, f1.x, acc[2]); acc[3] = fmaf(ph, f1.y, acc[3]);
    acc[4] = fmaf(ph, f2.x, acc[4]); acc[5] = fmaf(ph, f2.y, acc[5]);
    acc[6] = fmaf(ph, f3.x, acc[6]); acc[7] = fmaf(ph, f3.y, acc[7]);
}

__global__ __launch_bounds__(256)
void agg_kernel(const __half* __restrict__ Whh, float* __restrict__ out) {
    int warp = (blockIdx.x * blockDim.x + threadIdx.x) >> 5;
    int lane = threadIdx.x & 31;
    if (warp >= NN) return;
    int n = warp;
    int start = g_rowptr[n], end = g_rowptr[n + 1];
    float4 dn = *(const float4*)(g_ld + n * 4);

    float acc[8];
#pragma unroll
    for (int j = 0; j < 8; j++) acc[j] = 0.f;
    float z0 = 0.f, z1 = 0.f, z2 = 0.f, z3 = 0.f;
    int hsel = lane >> 3;

    int i = start;
    for (; i + 3 < end; i += 4) {
        int s0 = g_srcs[i], s1 = g_srcs[i + 1], s2 = g_srcs[i + 2], s3 = g_srcs[i + 3];
        float4 l0 = *(const float4*)(g_ls + s0 * 4);
        float4 l1 = *(const float4*)(g_ls + s1 * 4);
        float4 l2 = *(const float4*)(g_ls + s2 * 4);
        float4 l3 = *(const float4*)(g_ls + s3 * 4);
        uint4 w0 = *(const uint4*)(Whh + (size_t)s0 * HF + lane * 8);
        uint4 w1 = *(const uint4*)(Whh + (size_t)s1 * HF + lane * 8);
        uint4 w2 = *(const uint4*)(Whh + (size_t)s2 * HF + lane * 8);
        uint4 w3 = *(const uint4*)(Whh + (size_t)s3 * HF + lane * 8);

        float pa0 = __expf(lrelu(l0.x + dn.x)), pa1 = __expf(lrelu(l0.y + dn.y));
        float pa2 = __expf(lrelu(l0.z + dn.z)), pa3 = __expf(lrelu(l0.w + dn.w));
        float pb0 = __expf(lrelu(l1.x + dn.x)), pb1 = __expf(lrelu(l1.y + dn.y));
        float pb2 = __expf(lrelu(l1.z + dn.z)), pb3 = __expf(lrelu(l1.w + dn.w));
        float pc0 = __expf(lrelu(l2.x + dn.x)), pc1 = __expf(lrelu(l2.y + dn.y));
        float pc2 = __expf(lrelu(l2.z + dn.z)), pc3 = __expf(lrelu(l2.w + dn.w));
        float pd0 = __expf(lrelu(l3.x + dn.x)), pd1 = __expf(lrelu(l3.y + dn.y));
        float pd2 = __expf(lrelu(l3.z + dn.z)), pd3 = __expf(lrelu(l3.w + dn.w));
        z0 += pa0 + pb0 + pc0 + pd0;
        z1 += pa1 + pb1 + pc1 + pd1;
        z2 += pa2 + pb2 + pc2 + pd2;
        z3 += pa3 + pb3 + pc3 + pd3;
        float pha = (hsel == 0) ? pa0 : (hsel == 1) ? pa1 : (hsel == 2) ? pa2 : pa3;
        float phb = (hsel == 0) ? pb0 : (hsel == 1) ? pb1 : (hsel == 2) ? pb2 : pb3;
        float phc = (hsel == 0) ? pc0 : (hsel == 1) ? pc1 : (hsel == 2) ? pc2 : pc3;
        float phd = (hsel == 0) ? pd0 : (hsel == 1) ? pd1 : (hsel == 2) ? pd2 : pd3;
        acc_edge(acc, pha, w0);
        acc_edge(acc, phb, w1);
        acc_edge(acc, phc, w2);
        acc_edge(acc, phd, w3);
    }
    for (; i < end; i++) {
        int s = g_srcs[i];
        float4 l = *(const float4*)(g_ls + s * 4);
        uint4 w = *(const uint4*)(Whh + (size_t)s * HF + lane * 8);
        float p0 = __expf(lrelu(l.x + dn.x)), p1 = __expf(lrelu(l.y + dn.y));
        float p2 = __expf(lrelu(l.z + dn.z)), p3 = __expf(lrelu(l.w + dn.w));
        z0 += p0; z1 += p1; z2 += p2; z3 += p3;
        float ph = (hsel == 0) ? p0 : (hsel == 1) ? p1 : (hsel == 2) ? p2 : p3;
        acc_edge(acc, ph, w);
    }
    float zh = (hsel == 0) ? z0 : (hsel == 1) ? z1 : (hsel == 2) ? z2 : z3;
    float inv = 1.f / (zh + 1e-16f);
    float res[8];
#pragma unroll
    for (int j = 0; j < 8; j++) {
        float v = acc[j] * inv;
        res[j] = v > 0.f ? v : (__expf(v) - 1.f);  // ELU
    }
    float* o = out + (size_t)n * HF + lane * 8;
    *(float4*)o = make_float4(res[0], res[1], res[2], res[3]);
    *(float4*)(o + 4) = make_float4(res[4], res[5], res[6], res[7]);
}

// ---------------- segmented pooling (batch is sorted) ----------------
#define PN 128
__device__ __forceinline__ void pool_flush(int g, int f, float mx, float sm) {
    if (mx > -CUDART_INF_F) {
        int* amx = (int*)&g_mx[g * HF + f];
        if (mx >= 0.f) atomicMax(amx, __float_as_int(mx));
        else atomicMin((unsigned int*)amx, (unsigned int)__float_as_int(mx));
        atomicAdd(&g_sm[g * HF + f], sm);
    }
}
__global__ __launch_bounds__(256)
void pool_kernel(const float* __restrict__ x, const int* __restrict__ batch) {
    __shared__ int sb[PN];
    int b0 = blockIdx.x * PN;
    int cnt = NN - b0; if (cnt > PN) cnt = PN;
    for (int i = threadIdx.x; i < cnt; i += 256) sb[i] = batch[b0 + i];
    __syncthreads();
    int f = threadIdx.x;
    int g = sb[0];
    float mx = -CUDART_INF_F, sm = 0.f;
    int segc = 0;
    for (int i = 0; i < cnt; i++) {
        int gb = sb[i];
        if (gb != g) {
            pool_flush(g, f, mx, sm);
            if (f == 0) atomicAdd(&g_cnt[g], segc);
            g = gb; mx = -CUDART_INF_F; sm = 0.f; segc = 0;
        }
        float v = x[(size_t)(b0 + i) * HF + f];
        mx = fmaxf(mx, v); sm += v; segc++;
    }
    pool_flush(g, f, mx, sm);
    if (f == 0) atomicAdd(&g_cnt[g], segc);
}

// ---------------- finalize pool + linear ----------------
__global__ void final_kernel(const float* __restrict__ linW, const float* __restrict__ linb,
                             float* __restrict__ outp) {
    int t = blockIdx.x * blockDim.x + threadIdx.x;
    if (t >= GG * CC) return;
    int g = t / CC, c = t % CC;
    float cnt = fmaxf((float)g_cnt[g], 1.f);
    float inv = 1.f / cnt;
    float acc = linb[c];
    const float* mxr = g_mx + g * HF;
    const float* smr = g_sm + g * HF;
#pragma unroll 4
    for (int f = 0; f < HF; f++) {
        float mv = mxr[f];
        if (!isfinite(mv)) mv = 0.f;
        acc = fmaf(mv, linW[f * CC + c], acc);
    }
#pragma unroll 4
    for (int f = 0; f < HF; f++) {
        acc = fmaf(smr[f] * inv, linW[(HF + f) * CC + c], acc);
    }
    outp[t] = acc;
}

// ---------------- launch ----------------
extern "C" void kernel_launch(void* const* d_in, const int* in_sizes, int n_in,
                              void* d_out, int out_size) {
    const float* x      = (const float*)d_in[0];
    const int*   ei     = (const int*)d_in[1];
    const int*   batch  = (const int*)d_in[2];
    const float* W1     = (const float*)d_in[3];
    const float* a1s    = (const float*)d_in[4];
    const float* a1d    = (const float*)d_in[5];
    const float* W2     = (const float*)d_in[6];
    const float* a2s    = (const float*)d_in[7];
    const float* a2d    = (const float*)d_in[8];
    const float* linW   = (const float*)d_in[9];
    const float* linb   = (const float*)d_in[10];
    float* outp = (float*)d_out;

    __half* pWhh; cudaGetSymbolAddress((void**)&pWhh, g_Whh);
    float* pO1;  cudaGetSymbolAddress((void**)&pO1,  g_out1);
    float* pO2;  cudaGetSymbolAddress((void**)&pO2,  g_out2);

    dim3 g1(2, (NN + 127) / 128);
    int aggBlocks = (NN * 32 + 255) / 256;

    init_kernel<<<(GG * HF + 255) / 256, 256>>>();
    count_kernel<<<(EE + 255) / 256, 256>>>(ei);
    scan_kernel<<<1, 1024>>>();
    gemm_fused_kernel<FIN><<<g1, 256>>>(x, W1, pWhh, a1s, a1d, NN);   // profiled slot
    scatter_kernel<<<(EE + 255) / 256, 256>>>(ei);
    agg_kernel<<<aggBlocks, 256>>>(pWhh, pO1);

    gemm_fused_kernel<HF><<<g1, 256>>>(pO1, W2, pWhh, a2s, a2d, NN);
    agg_kernel<<<aggBlocks, 256>>>(pWhh, pO2);

    pool_kernel<<<(NN + PN - 1) / PN, 256>>>(pO2, batch);
    final_kernel<<<(GG * CC + 255) / 256, 256>>>(linW, linb, outp);
}

// round 10
// speedup vs baseline: 1.4066x; 1.0993x over previous
#include <cuda_runtime.h>
#include <cuda_fp16.h>
#include <math_constants.h>

#define NN 50000
#define EE 800000
#define FIN 128
#define HF 256      // HEADS*HID = 4*64
#define GG 256
#define CC 10

typedef unsigned long long ull;

// ---------------- scratch (no allocations allowed) ----------------
__device__ __half g_Whh[(size_t)NN * HF];   // Wh in fp16 (gather source)
__device__ float g_out1[(size_t)NN * HF];
__device__ float g_out2[(size_t)NN * HF];
__device__ float g_ls[NN * 4];
__device__ float g_ld[NN * 4];
__device__ int   g_deg[NN];
__device__ int   g_rowptr[NN + 1];
__device__ int   g_cursor[NN];
__device__ int   g_srcs[EE];
__device__ float g_mx[GG * HF];
__device__ float g_sm[GG * HF];
__device__ int   g_cnt[GG];

__device__ __forceinline__ ull pack2(float lo, float hi) {
    ull r;
    asm("mov.b64 %0, {%1, %2};" : "=l"(r) : "f"(lo), "f"(hi));
    return r;
}
__device__ __forceinline__ void unpack2(ull v, float& lo, float& hi) {
    asm("mov.b64 {%0, %1}, %2;" : "=f"(lo), "=f"(hi) : "l"(v));
}
__device__ __forceinline__ void ffma2(ull& acc, ull a, ull b) {
    asm("fma.rn.f32x2 %0, %1, %2, %0;" : "+l"(acc) : "l"(a), "l"(b));
}
__device__ __forceinline__ unsigned f16x2_of(float lo, float hi) {
    unsigned r;
    asm("cvt.rn.f16x2.f32 %0, %1, %2;" : "=r"(r) : "f"(hi), "f"(lo));  // first src -> high half
    return r;
}
__device__ __forceinline__ float2 h2f(unsigned u) {
    __half2 h = *reinterpret_cast<__half2*>(&u);
    return __half22float2(h);
}
__device__ __forceinline__ void cp16(void* smem_dst, const void* gsrc) {
    unsigned s = (unsigned)__cvta_generic_to_shared(smem_dst);
    asm volatile("cp.async.cg.shared.global [%0], [%1], 16;" :: "r"(s), "l"(gsrc));
}
__device__ __forceinline__ void cp_commit() { asm volatile("cp.async.commit_group;"); }
__device__ __forceinline__ void cp_wait1() { asm volatile("cp.async.wait_group 1;"); }
__device__ __forceinline__ void cp_wait0() { asm volatile("cp.async.wait_group 0;"); }

// ---------------- init ----------------
__global__ void init_kernel() {
    int i = blockIdx.x * blockDim.x + threadIdx.x;
    if (i < NN) g_deg[i] = 0;
    if (i < GG * HF) { g_mx[i] = -CUDART_INF_F; g_sm[i] = 0.f; }
    if (i < GG) g_cnt[i] = 0;
}

// ---------------- CSR build ----------------
__global__ void count_kernel(const int* __restrict__ ei) {
    int e = blockIdx.x * blockDim.x + threadIdx.x;
    if (e >= EE) return;
    atomicAdd(&g_deg[ei[EE + e]], 1);
}

__global__ void scan_kernel() {
    const int T = 1024;
    int tid = threadIdx.x;
    int per = (NN + T - 1) / T;
    int start = tid * per;
    int end = start + per; if (end > NN) end = NN; if (start > NN) start = NN;
    int s = 0;
    for (int i = start; i < end; i++) s += g_deg[i];
    __shared__ int sums[T];
    sums[tid] = s;
    __syncthreads();
    for (int off = 1; off < T; off <<= 1) {
        int v = (tid >= off) ? sums[tid - off] : 0;
        __syncthreads();
        sums[tid] += v;
        __syncthreads();
    }
    int run = (tid > 0) ? sums[tid - 1] : 0;
    for (int i = start; i < end; i++) {
        g_rowptr[i] = run;
        g_cursor[i] = run;
        run += g_deg[i];
    }
    if (tid == T - 1) g_rowptr[NN] = run;
}

__global__ void scatter_kernel(const int* __restrict__ ei) {
    int e = blockIdx.x * blockDim.x + threadIdx.x;
    if (e >= EE) return;
    int dst = ei[EE + e];
    int pos = atomicAdd(&g_cursor[dst], 1);
    g_srcs[pos] = ei[e];
}

// ---- GEMM + fused logits: Whh[M,256] = fp16(A[M,K]*B[K,256]) ----
// 8x8 f32x2 tile, cp.async 2-stage double buffer, BK=32 (dynamic smem).
#define GEMM_SMEM (2 * 128 * 32 * 4 + 2 * 32 * 128 * 4 + 2 * 128 * 4)
template <int K>
__global__ __launch_bounds__(256, 2)
void gemm_fused_kernel(const float* __restrict__ A, const float* __restrict__ B,
                       __half* __restrict__ Whh,
                       const float* __restrict__ a_src, const float* __restrict__ a_dst,
                       int M) {
    constexpr int BM = 128, BN = 128, BK = 32;
    constexpr int T = K / BK;                       // 4 or 8 k-tiles
    extern __shared__ __align__(16) char smem_raw[];
    float (*As)[BM][BK] = reinterpret_cast<float(*)[BM][BK]>(smem_raw);
    float (*Bs)[BK][BN] = reinterpret_cast<float(*)[BK][BN]>(smem_raw + 2 * BM * BK * 4);
    float* s_as = (float*)(smem_raw + 4 * BM * BK * 4);
    float* s_ad = s_as + BN;

    int tid = threadIdx.x;
    int tx = tid & 15, ty = tid >> 4;
    int m0 = blockIdx.y * BM, n0 = blockIdx.x * BN;   // n0 in {0,128}
    if (tid < BN) { s_as[tid] = a_src[n0 + tid]; s_ad[tid] = a_dst[n0 + tid]; }

    ull acc2[8][4];
#pragma unroll
    for (int i = 0; i < 8; i++)
#pragma unroll
        for (int j = 0; j < 4; j++) acc2[i][j] = 0ull;

    // async-load one BK=32 tile into stage st
    auto issue = [&](int st, int k0) {
#pragma unroll
        for (int u = 0; u < 4; u++) {
            int ch = tid + u * 256;                  // 0..1023
            int m = ch >> 3, kq = (ch & 7) * 4;      // A: 128 rows x 8 chunks
            int gm = m0 + m; if (gm >= M) gm = M - 1;
            cp16(&As[st][m][kq], &A[(size_t)gm * K + k0 + kq]);
            int r = ch >> 5, cq = (ch & 31) * 4;     // B: 32 rows x 32 chunks
            cp16(&Bs[st][r][cq], &B[(size_t)(k0 + r) * 256 + n0 + cq]);
        }
        cp_commit();
    };

    issue(0, 0);

#pragma unroll 1
    for (int t = 0; t < T; t++) {
        int st = t & 1;
        if (t + 1 < T) { issue(st ^ 1, (t + 1) * BK); cp_wait1(); }
        else           { cp_wait0(); }
        __syncthreads();
#pragma unroll
        for (int kk = 0; kk < BK / 2; kk++) {
            ulonglong2 q0 = *(const ulonglong2*)&Bs[st][2 * kk][tx * 4];
            ulonglong2 q1 = *(const ulonglong2*)&Bs[st][2 * kk][64 + tx * 4];
            ulonglong2 r0 = *(const ulonglong2*)&Bs[st][2 * kk + 1][tx * 4];
            ulonglong2 r1 = *(const ulonglong2*)&Bs[st][2 * kk + 1][64 + tx * 4];
#pragma unroll
            for (int i = 0; i < 8; i++) {
                float2 ap = *(const float2*)&As[st][ty * 8 + i][2 * kk];
                ull a0 = pack2(ap.x, ap.x);
                ull a1 = pack2(ap.y, ap.y);
                ffma2(acc2[i][0], a0, q0.x);
                ffma2(acc2[i][1], a0, q0.y);
                ffma2(acc2[i][2], a0, q1.x);
                ffma2(acc2[i][3], a0, q1.y);
                ffma2(acc2[i][0], a1, r0.x);
                ffma2(acc2[i][1], a1, r0.y);
                ffma2(acc2[i][2], a1, r1.x);
                ffma2(acc2[i][3], a1, r1.y);
            }
        }
        __syncthreads();
    }

    int h0 = n0 >> 6;  // first head this block owns (0 or 2)
#pragma unroll
    for (int i = 0; i < 8; i++) {
        int gm = m0 + ty * 8 + i;
        float c0, c1, c2, c3, c4, c5, c6, c7;
        unpack2(acc2[i][0], c0, c1);
        unpack2(acc2[i][1], c2, c3);
        unpack2(acc2[i][2], c4, c5);
        unpack2(acc2[i][3], c6, c7);
        if (gm < M) {
            unsigned p0 = f16x2_of(c0, c1);
            unsigned p1 = f16x2_of(c2, c3);
            unsigned p2 = f16x2_of(c4, c5);
            unsigned p3 = f16x2_of(c6, c7);
            *(uint2*)&Whh[(size_t)gm * 256 + n0 + tx * 4] = make_uint2(p0, p1);
            *(uint2*)&Whh[(size_t)gm * 256 + n0 + 64 + tx * 4] = make_uint2(p2, p3);
        }
        int f = tx * 4;
        float lsA = c0 * s_as[f] + c1 * s_as[f + 1] + c2 * s_as[f + 2] + c3 * s_as[f + 3];
        float ldA = c0 * s_ad[f] + c1 * s_ad[f + 1] + c2 * s_ad[f + 2] + c3 * s_ad[f + 3];
        float lsB = c4 * s_as[64 + f] + c5 * s_as[64 + f + 1] + c6 * s_as[64 + f + 2] + c7 * s_as[64 + f + 3];
        float ldB = c4 * s_ad[64 + f] + c5 * s_ad[64 + f + 1] + c6 * s_ad[64 + f + 2] + c7 * s_ad[64 + f + 3];
#pragma unroll
        for (int off = 8; off >= 1; off >>= 1) {
            lsA += __shfl_xor_sync(0xffffffffu, lsA, off);
            ldA += __shfl_xor_sync(0xffffffffu, ldA, off);
            lsB += __shfl_xor_sync(0xffffffffu, lsB, off);
            ldB += __shfl_xor_sync(0xffffffffu, ldB, off);
        }
        if (tx == 0 && gm < M) {
            g_ls[gm * 4 + h0]     = lsA;
            g_ls[gm * 4 + h0 + 1] = lsB;
            g_ld[gm * 4 + h0]     = ldA;
            g_ld[gm * 4 + h0 + 1] = ldB;
        }
    }
}

// ---- fused edge-softmax + aggregation + ELU (warp per dst) ----
// Each lane handles ONLY its own head (hsel = lane>>3): scalar logit load,
// one lrelu (fmax(v, 0.01v)) + one expf per edge; own-head z accumulation.
__device__ __forceinline__ void acc_edge(float* acc, float ph, uint4 w) {
    float2 f0 = h2f(w.x), f1 = h2f(w.y), f2 = h2f(w.z), f3 = h2f(w.w);
    acc[0] = fmaf(ph, f0.x, acc[0]); acc[1] = fmaf(ph, f0.y, acc[1]);
    acc[2] = fmaf(ph, f1.x, acc[2]); acc[3] = fmaf(ph, f1.y, acc[3]);
    acc[4] = fmaf(ph, f2.x, acc[4]); acc[5] = fmaf(ph, f2.y, acc[5]);
    acc[6] = fmaf(ph, f3.x, acc[6]); acc[7] = fmaf(ph, f3.y, acc[7]);
}

__global__ __launch_bounds__(256)
void agg_kernel(const __half* __restrict__ Whh, float* __restrict__ out) {
    int warp = (blockIdx.x * blockDim.x + threadIdx.x) >> 5;
    int lane = threadIdx.x & 31;
    if (warp >= NN) return;
    int n = warp;
    int start = g_rowptr[n], end = g_rowptr[n + 1];
    int hsel = lane >> 3;
    float dnh = g_ld[n * 4 + hsel];

    float acc[8];
#pragma unroll
    for (int j = 0; j < 8; j++) acc[j] = 0.f;
    float zh = 0.f;

    int i = start;
    for (; i + 3 < end; i += 4) {
        int s0 = g_srcs[i], s1 = g_srcs[i + 1], s2 = g_srcs[i + 2], s3 = g_srcs[i + 3];
        float e0 = g_ls[s0 * 4 + hsel] + dnh;
        float e1 = g_ls[s1 * 4 + hsel] + dnh;
        float e2 = g_ls[s2 * 4 + hsel] + dnh;
        float e3 = g_ls[s3 * 4 + hsel] + dnh;
        uint4 w0 = *(const uint4*)(Whh + (size_t)s0 * HF + lane * 8);
        uint4 w1 = *(const uint4*)(Whh + (size_t)s1 * HF + lane * 8);
        uint4 w2 = *(const uint4*)(Whh + (size_t)s2 * HF + lane * 8);
        uint4 w3 = *(const uint4*)(Whh + (size_t)s3 * HF + lane * 8);
        float p0 = __expf(fmaxf(e0, 0.01f * e0));
        float p1 = __expf(fmaxf(e1, 0.01f * e1));
        float p2 = __expf(fmaxf(e2, 0.01f * e2));
        float p3 = __expf(fmaxf(e3, 0.01f * e3));
        zh += p0 + p1 + p2 + p3;
        acc_edge(acc, p0, w0);
        acc_edge(acc, p1, w1);
        acc_edge(acc, p2, w2);
        acc_edge(acc, p3, w3);
    }
    for (; i < end; i++) {
        int s = g_srcs[i];
        float e = g_ls[s * 4 + hsel] + dnh;
        uint4 w = *(const uint4*)(Whh + (size_t)s * HF + lane * 8);
        float p = __expf(fmaxf(e, 0.01f * e));
        zh += p;
        acc_edge(acc, p, w);
    }
    float inv = 1.f / (zh + 1e-16f);
    float res[8];
#pragma unroll
    for (int j = 0; j < 8; j++) {
        float v = acc[j] * inv;
        res[j] = v > 0.f ? v : (__expf(v) - 1.f);  // ELU
    }
    float* o = out + (size_t)n * HF + lane * 8;
    *(float4*)o = make_float4(res[0], res[1], res[2], res[3]);
    *(float4*)(o + 4) = make_float4(res[4], res[5], res[6], res[7]);
}

// ---------------- segmented pooling (batch is sorted) ----------------
#define PN 128
__device__ __forceinline__ void pool_flush(int g, int f, float mx, float sm) {
    if (mx > -CUDART_INF_F) {
        int* amx = (int*)&g_mx[g * HF + f];
        if (mx >= 0.f) atomicMax(amx, __float_as_int(mx));
        else atomicMin((unsigned int*)amx, (unsigned int)__float_as_int(mx));
        atomicAdd(&g_sm[g * HF + f], sm);
    }
}
__global__ __launch_bounds__(256)
void pool_kernel(const float* __restrict__ x, const int* __restrict__ batch) {
    __shared__ int sb[PN];
    int b0 = blockIdx.x * PN;
    int cnt = NN - b0; if (cnt > PN) cnt = PN;
    for (int i = threadIdx.x; i < cnt; i += 256) sb[i] = batch[b0 + i];
    __syncthreads();
    int f = threadIdx.x;
    int g = sb[0];
    float mx = -CUDART_INF_F, sm = 0.f;
    int segc = 0;
    for (int i = 0; i < cnt; i++) {
        int gb = sb[i];
        if (gb != g) {
            pool_flush(g, f, mx, sm);
            if (f == 0) atomicAdd(&g_cnt[g], segc);
            g = gb; mx = -CUDART_INF_F; sm = 0.f; segc = 0;
        }
        float v = x[(size_t)(b0 + i) * HF + f];
        mx = fmaxf(mx, v); sm += v; segc++;
    }
    pool_flush(g, f, mx, sm);
    if (f == 0) atomicAdd(&g_cnt[g], segc);
}

// ---------------- finalize pool + linear ----------------
__global__ void final_kernel(const float* __restrict__ linW, const float* __restrict__ linb,
                             float* __restrict__ outp) {
    int t = blockIdx.x * blockDim.x + threadIdx.x;
    if (t >= GG * CC) return;
    int g = t / CC, c = t % CC;
    float cnt = fmaxf((float)g_cnt[g], 1.f);
    float inv = 1.f / cnt;
    float acc = linb[c];
    const float* mxr = g_mx + g * HF;
    const float* smr = g_sm + g * HF;
#pragma unroll 4
    for (int f = 0; f < HF; f++) {
        float mv = mxr[f];
        if (!isfinite(mv)) mv = 0.f;
        acc = fmaf(mv, linW[f * CC + c], acc);
    }
#pragma unroll 4
    for (int f = 0; f < HF; f++) {
        acc = fmaf(smr[f] * inv, linW[(HF + f) * CC + c], acc);
    }
    outp[t] = acc;
}

// ---------------- launch ----------------
extern "C" void kernel_launch(void* const* d_in, const int* in_sizes, int n_in,
                              void* d_out, int out_size) {
    const float* x      = (const float*)d_in[0];
    const int*   ei     = (const int*)d_in[1];
    const int*   batch  = (const int*)d_in[2];
    const float* W1     = (const float*)d_in[3];
    const float* a1s    = (const float*)d_in[4];
    const float* a1d    = (const float*)d_in[5];
    const float* W2     = (const float*)d_in[6];
    const float* a2s    = (const float*)d_in[7];
    const float* a2d    = (const float*)d_in[8];
    const float* linW   = (const float*)d_in[9];
    const float* linb   = (const float*)d_in[10];
    float* outp = (float*)d_out;

    __half* pWhh; cudaGetSymbolAddress((void**)&pWhh, g_Whh);
    float* pO1;  cudaGetSymbolAddress((void**)&pO1,  g_out1);
    float* pO2;  cudaGetSymbolAddress((void**)&pO2,  g_out2);

    static int attr_done = 0;
    if (!attr_done) {
        cudaFuncSetAttribute(gemm_fused_kernel<FIN>,
                             cudaFuncAttributeMaxDynamicSharedMemorySize, GEMM_SMEM);
        cudaFuncSetAttribute(gemm_fused_kernel<HF>,
                             cudaFuncAttributeMaxDynamicSharedMemorySize, GEMM_SMEM);
        attr_done = 1;
    }

    dim3 g1(2, (NN + 127) / 128);
    int aggBlocks = (NN * 32 + 255) / 256;

    init_kernel<<<(GG * HF + 255) / 256, 256>>>();
    count_kernel<<<(EE + 255) / 256, 256>>>(ei);
    scan_kernel<<<1, 1024>>>();
    gemm_fused_kernel<FIN><<<g1, 256, GEMM_SMEM>>>(x, W1, pWhh, a1s, a1d, NN);  // profiled slot
    scatter_kernel<<<(EE + 255) / 256, 256>>>(ei);
    agg_kernel<<<aggBlocks, 256>>>(pWhh, pO1);

    gemm_fused_kernel<HF><<<g1, 256, GEMM_SMEM>>>(pO1, W2, pWhh, a2s, a2d, NN);
    agg_kernel<<<aggBlocks, 256>>>(pWhh, pO2);

    pool_kernel<<<(NN + PN - 1) / PN, 256>>>(pO2, batch);
    final_kernel<<<(GG * CC + 255) / 256, 256>>>(linW, linb, outp);
}

// round 11
// speedup vs baseline: 1.4286x; 1.0156x over previous
#include <cuda_runtime.h>
#include <cuda_fp16.h>
#include <math_constants.h>

#define NN 50000
#define EE 800000
#define FIN 128
#define HF 256      // HEADS*HID = 4*64
#define GG 256
#define CC 10

typedef unsigned long long ull;

// ---------------- scratch (no allocations allowed) ----------------
__device__ __half g_Whh[(size_t)NN * HF];   // Wh in fp16 (gather source)
__device__ float g_out1[(size_t)NN * HF];
__device__ float g_out2[(size_t)NN * HF];
__device__ float g_ls[NN * 4];
__device__ float g_ld[NN * 4];
__device__ int   g_deg[NN];
__device__ int   g_rowptr[NN + 1];
__device__ int   g_cursor[NN];
__device__ int   g_srcs[EE];
__device__ float g_mx[GG * HF];
__device__ float g_sm[GG * HF];
__device__ int   g_cnt[GG];

__device__ __forceinline__ ull pack2(float lo, float hi) {
    ull r;
    asm("mov.b64 %0, {%1, %2};" : "=l"(r) : "f"(lo), "f"(hi));
    return r;
}
__device__ __forceinline__ void unpack2(ull v, float& lo, float& hi) {
    asm("mov.b64 {%0, %1}, %2;" : "=f"(lo), "=f"(hi) : "l"(v));
}
__device__ __forceinline__ void ffma2(ull& acc, ull a, ull b) {
    asm("fma.rn.f32x2 %0, %1, %2, %0;" : "+l"(acc) : "l"(a), "l"(b));
}
__device__ __forceinline__ unsigned f16x2_of(float lo, float hi) {
    unsigned r;
    asm("cvt.rn.f16x2.f32 %0, %1, %2;" : "=r"(r) : "f"(hi), "f"(lo));  // first src -> high half
    return r;
}
__device__ __forceinline__ float2 h2f(unsigned u) {
    __half2 h = *reinterpret_cast<__half2*>(&u);
    return __half22float2(h);
}
__device__ __forceinline__ void cp16(void* smem_dst, const void* gsrc) {
    unsigned s = (unsigned)__cvta_generic_to_shared(smem_dst);
    asm volatile("cp.async.cg.shared.global [%0], [%1], 16;" :: "r"(s), "l"(gsrc));
}
__device__ __forceinline__ void cp_commit() { asm volatile("cp.async.commit_group;"); }
__device__ __forceinline__ void cp_wait1() { asm volatile("cp.async.wait_group 1;"); }
__device__ __forceinline__ void cp_wait0() { asm volatile("cp.async.wait_group 0;"); }

// ---------------- init ----------------
__global__ void init_kernel() {
    int i = blockIdx.x * blockDim.x + threadIdx.x;
    if (i < NN) g_deg[i] = 0;
    if (i < GG * HF) { g_mx[i] = -CUDART_INF_F; g_sm[i] = 0.f; }
    if (i < GG) g_cnt[i] = 0;
}

// ---------------- CSR build ----------------
__global__ void count_kernel(const int* __restrict__ ei) {
    int e = blockIdx.x * blockDim.x + threadIdx.x;
    if (e >= EE) return;
    atomicAdd(&g_deg[ei[EE + e]], 1);
}

__global__ void scan_kernel() {
    const int T = 1024;
    int tid = threadIdx.x;
    int per = (NN + T - 1) / T;
    int start = tid * per;
    int end = start + per; if (end > NN) end = NN; if (start > NN) start = NN;
    int s = 0;
    for (int i = start; i < end; i++) s += g_deg[i];
    __shared__ int sums[T];
    sums[tid] = s;
    __syncthreads();
    for (int off = 1; off < T; off <<= 1) {
        int v = (tid >= off) ? sums[tid - off] : 0;
        __syncthreads();
        sums[tid] += v;
        __syncthreads();
    }
    int run = (tid > 0) ? sums[tid - 1] : 0;
    for (int i = start; i < end; i++) {
        g_rowptr[i] = run;
        g_cursor[i] = run;
        run += g_deg[i];
    }
    if (tid == T - 1) g_rowptr[NN] = run;
}

__global__ void scatter_kernel(const int* __restrict__ ei) {
    int e = blockIdx.x * blockDim.x + threadIdx.x;
    if (e >= EE) return;
    int dst = ei[EE + e];
    int pos = atomicAdd(&g_cursor[dst], 1);
    g_srcs[pos] = ei[e];
}

// ---- GEMM + fused logits: Whh[M,256] = fp16(A[M,K]*B[K,256]) ----
// 8x8 f32x2 tile, cp.async 2-stage double buffer, BK=32 (dynamic smem).
#define GEMM_SMEM (2 * 128 * 32 * 4 + 2 * 32 * 128 * 4 + 2 * 128 * 4)
template <int K>
__global__ __launch_bounds__(256, 2)
void gemm_fused_kernel(const float* __restrict__ A, const float* __restrict__ B,
                       __half* __restrict__ Whh,
                       const float* __restrict__ a_src, const float* __restrict__ a_dst,
                       int M) {
    constexpr int BM = 128, BN = 128, BK = 32;
    constexpr int T = K / BK;                       // 4 or 8 k-tiles
    extern __shared__ __align__(16) char smem_raw[];
    float (*As)[BM][BK] = reinterpret_cast<float(*)[BM][BK]>(smem_raw);
    float (*Bs)[BK][BN] = reinterpret_cast<float(*)[BK][BN]>(smem_raw + 2 * BM * BK * 4);
    float* s_as = (float*)(smem_raw + 4 * BM * BK * 4);
    float* s_ad = s_as + BN;

    int tid = threadIdx.x;
    int tx = tid & 15, ty = tid >> 4;
    int m0 = blockIdx.y * BM, n0 = blockIdx.x * BN;   // n0 in {0,128}
    if (tid < BN) { s_as[tid] = a_src[n0 + tid]; s_ad[tid] = a_dst[n0 + tid]; }

    ull acc2[8][4];
#pragma unroll
    for (int i = 0; i < 8; i++)
#pragma unroll
        for (int j = 0; j < 4; j++) acc2[i][j] = 0ull;

    // async-load one BK=32 tile into stage st
    auto issue = [&](int st, int k0) {
#pragma unroll
        for (int u = 0; u < 4; u++) {
            int ch = tid + u * 256;                  // 0..1023
            int m = ch >> 3, kq = (ch & 7) * 4;      // A: 128 rows x 8 chunks
            int gm = m0 + m; if (gm >= M) gm = M - 1;
            cp16(&As[st][m][kq], &A[(size_t)gm * K + k0 + kq]);
            int r = ch >> 5, cq = (ch & 31) * 4;     // B: 32 rows x 32 chunks
            cp16(&Bs[st][r][cq], &B[(size_t)(k0 + r) * 256 + n0 + cq]);
        }
        cp_commit();
    };

    issue(0, 0);

#pragma unroll 1
    for (int t = 0; t < T; t++) {
        int st = t & 1;
        if (t + 1 < T) { issue(st ^ 1, (t + 1) * BK); cp_wait1(); }
        else           { cp_wait0(); }
        __syncthreads();
#pragma unroll
        for (int kk = 0; kk < BK / 2; kk++) {
            ulonglong2 q0 = *(const ulonglong2*)&Bs[st][2 * kk][tx * 4];
            ulonglong2 q1 = *(const ulonglong2*)&Bs[st][2 * kk][64 + tx * 4];
            ulonglong2 r0 = *(const ulonglong2*)&Bs[st][2 * kk + 1][tx * 4];
            ulonglong2 r1 = *(const ulonglong2*)&Bs[st][2 * kk + 1][64 + tx * 4];
#pragma unroll
            for (int i = 0; i < 8; i++) {
                float2 ap = *(const float2*)&As[st][ty * 8 + i][2 * kk];
                ull a0 = pack2(ap.x, ap.x);
                ull a1 = pack2(ap.y, ap.y);
                ffma2(acc2[i][0], a0, q0.x);
                ffma2(acc2[i][1], a0, q0.y);
                ffma2(acc2[i][2], a0, q1.x);
                ffma2(acc2[i][3], a0, q1.y);
                ffma2(acc2[i][0], a1, r0.x);
                ffma2(acc2[i][1], a1, r0.y);
                ffma2(acc2[i][2], a1, r1.x);
                ffma2(acc2[i][3], a1, r1.y);
            }
        }
        __syncthreads();
    }

    int h0 = n0 >> 6;  // first head this block owns (0 or 2)
#pragma unroll
    for (int i = 0; i < 8; i++) {
        int gm = m0 + ty * 8 + i;
        float c0, c1, c2, c3, c4, c5, c6, c7;
        unpack2(acc2[i][0], c0, c1);
        unpack2(acc2[i][1], c2, c3);
        unpack2(acc2[i][2], c4, c5);
        unpack2(acc2[i][3], c6, c7);
        if (gm < M) {
            unsigned p0 = f16x2_of(c0, c1);
            unsigned p1 = f16x2_of(c2, c3);
            unsigned p2 = f16x2_of(c4, c5);
            unsigned p3 = f16x2_of(c6, c7);
            *(uint2*)&Whh[(size_t)gm * 256 + n0 + tx * 4] = make_uint2(p0, p1);
            *(uint2*)&Whh[(size_t)gm * 256 + n0 + 64 + tx * 4] = make_uint2(p2, p3);
        }
        int f = tx * 4;
        float lsA = c0 * s_as[f] + c1 * s_as[f + 1] + c2 * s_as[f + 2] + c3 * s_as[f + 3];
        float ldA = c0 * s_ad[f] + c1 * s_ad[f + 1] + c2 * s_ad[f + 2] + c3 * s_ad[f + 3];
        float lsB = c4 * s_as[64 + f] + c5 * s_as[64 + f + 1] + c6 * s_as[64 + f + 2] + c7 * s_as[64 + f + 3];
        float ldB = c4 * s_ad[64 + f] + c5 * s_ad[64 + f + 1] + c6 * s_ad[64 + f + 2] + c7 * s_ad[64 + f + 3];
#pragma unroll
        for (int off = 8; off >= 1; off >>= 1) {
            lsA += __shfl_xor_sync(0xffffffffu, lsA, off);
            ldA += __shfl_xor_sync(0xffffffffu, ldA, off);
            lsB += __shfl_xor_sync(0xffffffffu, lsB, off);
            ldB += __shfl_xor_sync(0xffffffffu, ldB, off);
        }
        if (tx == 0 && gm < M) {
            g_ls[gm * 4 + h0]     = lsA;
            g_ls[gm * 4 + h0 + 1] = lsB;
            g_ld[gm * 4 + h0]     = ldA;
            g_ld[gm * 4 + h0 + 1] = ldB;
        }
    }
}

// ---- fused edge-softmax + aggregation + ELU (warp per dst) ----
// Head-specialized lanes; 8-edge batched loads for deep MLP.
__device__ __forceinline__ void acc_edge(float* acc, float ph, uint4 w) {
    float2 f0 = h2f(w.x), f1 = h2f(w.y), f2 = h2f(w.z), f3 = h2f(w.w);
    acc[0] = fmaf(ph, f0.x, acc[0]); acc[1] = fmaf(ph, f0.y, acc[1]);
    acc[2] = fmaf(ph, f1.x, acc[2]); acc[3] = fmaf(ph, f1.y, acc[3]);
    acc[4] = fmaf(ph, f2.x, acc[4]); acc[5] = fmaf(ph, f2.y, acc[5]);
    acc[6] = fmaf(ph, f3.x, acc[6]); acc[7] = fmaf(ph, f3.y, acc[7]);
}

__global__ __launch_bounds__(256)
void agg_kernel(const __half* __restrict__ Whh, float* __restrict__ out) {
    int warp = (blockIdx.x * blockDim.x + threadIdx.x) >> 5;
    int lane = threadIdx.x & 31;
    if (warp >= NN) return;
    int n = warp;
    int start = g_rowptr[n], end = g_rowptr[n + 1];
    int hsel = lane >> 3;
    float dnh = g_ld[n * 4 + hsel];

    float acc[8];
#pragma unroll
    for (int j = 0; j < 8; j++) acc[j] = 0.f;
    float zh = 0.f;

    int i = start;
    for (; i + 7 < end; i += 8) {
        int s[8];
#pragma unroll
        for (int u = 0; u < 8; u++) s[u] = g_srcs[i + u];
        uint4 w[8];
#pragma unroll
        for (int u = 0; u < 8; u++)
            w[u] = *(const uint4*)(Whh + (size_t)s[u] * HF + lane * 8);
        float e[8];
#pragma unroll
        for (int u = 0; u < 8; u++) e[u] = g_ls[s[u] * 4 + hsel] + dnh;
#pragma unroll
        for (int u = 0; u < 8; u++) {
            float p = __expf(fmaxf(e[u], 0.01f * e[u]));
            zh += p;
            acc_edge(acc, p, w[u]);
        }
    }
    for (; i + 3 < end; i += 4) {
        int s[4];
#pragma unroll
        for (int u = 0; u < 4; u++) s[u] = g_srcs[i + u];
        uint4 w[4];
#pragma unroll
        for (int u = 0; u < 4; u++)
            w[u] = *(const uint4*)(Whh + (size_t)s[u] * HF + lane * 8);
#pragma unroll
        for (int u = 0; u < 4; u++) {
            float e = g_ls[s[u] * 4 + hsel] + dnh;
            float p = __expf(fmaxf(e, 0.01f * e));
            zh += p;
            acc_edge(acc, p, w[u]);
        }
    }
    for (; i < end; i++) {
        int s = g_srcs[i];
        float e = g_ls[s * 4 + hsel] + dnh;
        uint4 w = *(const uint4*)(Whh + (size_t)s * HF + lane * 8);
        float p = __expf(fmaxf(e, 0.01f * e));
        zh += p;
        acc_edge(acc, p, w);
    }
    float inv = 1.f / (zh + 1e-16f);
    float res[8];
#pragma unroll
    for (int j = 0; j < 8; j++) {
        float v = acc[j] * inv;
        res[j] = v > 0.f ? v : (__expf(v) - 1.f);  // ELU
    }
    float* o = out + (size_t)n * HF + lane * 8;
    *(float4*)o = make_float4(res[0], res[1], res[2], res[3]);
    *(float4*)(o + 4) = make_float4(res[4], res[5], res[6], res[7]);
}

// ---------------- segmented pooling (batch is sorted) ----------------
#define PN 128
__device__ __forceinline__ void pool_flush(int g, int f, float mx, float sm) {
    if (mx > -CUDART_INF_F) {
        int* amx = (int*)&g_mx[g * HF + f];
        if (mx >= 0.f) atomicMax(amx, __float_as_int(mx));
        else atomicMin((unsigned int*)amx, (unsigned int)__float_as_int(mx));
        atomicAdd(&g_sm[g * HF + f], sm);
    }
}
__global__ __launch_bounds__(256)
void pool_kernel(const float* __restrict__ x, const int* __restrict__ batch) {
    __shared__ int sb[PN];
    int b0 = blockIdx.x * PN;
    int cnt = NN - b0; if (cnt > PN) cnt = PN;
    for (int i = threadIdx.x; i < cnt; i += 256) sb[i] = batch[b0 + i];
    __syncthreads();
    int f = threadIdx.x;
    int g = sb[0];
    float mx = -CUDART_INF_F, sm = 0.f;
    int segc = 0;
    for (int i = 0; i < cnt; i++) {
        int gb = sb[i];
        if (gb != g) {
            pool_flush(g, f, mx, sm);
            if (f == 0) atomicAdd(&g_cnt[g], segc);
            g = gb; mx = -CUDART_INF_F; sm = 0.f; segc = 0;
        }
        float v = x[(size_t)(b0 + i) * HF + f];
        mx = fmaxf(mx, v); sm += v; segc++;
    }
    pool_flush(g, f, mx, sm);
    if (f == 0) atomicAdd(&g_cnt[g], segc);
}

// ---------------- finalize pool + linear ----------------
__global__ void final_kernel(const float* __restrict__ linW, const float* __restrict__ linb,
                             float* __restrict__ outp) {
    int t = blockIdx.x * blockDim.x + threadIdx.x;
    if (t >= GG * CC) return;
    int g = t / CC, c = t % CC;
    float cnt = fmaxf((float)g_cnt[g], 1.f);
    float inv = 1.f / cnt;
    float acc = linb[c];
    const float* mxr = g_mx + g * HF;
    const float* smr = g_sm + g * HF;
#pragma unroll 4
    for (int f = 0; f < HF; f++) {
        float mv = mxr[f];
        if (!isfinite(mv)) mv = 0.f;
        acc = fmaf(mv, linW[f * CC + c], acc);
    }
#pragma unroll 4
    for (int f = 0; f < HF; f++) {
        acc = fmaf(smr[f] * inv, linW[(HF + f) * CC + c], acc);
    }
    outp[t] = acc;
}

// ---------------- launch ----------------
extern "C" void kernel_launch(void* const* d_in, const int* in_sizes, int n_in,
                              void* d_out, int out_size) {
    const float* x      = (const float*)d_in[0];
    const int*   ei     = (const int*)d_in[1];
    const int*   batch  = (const int*)d_in[2];
    const float* W1     = (const float*)d_in[3];
    const float* a1s    = (const float*)d_in[4];
    const float* a1d    = (const float*)d_in[5];
    const float* W2     = (const float*)d_in[6];
    const float* a2s    = (const float*)d_in[7];
    const float* a2d    = (const float*)d_in[8];
    const float* linW   = (const float*)d_in[9];
    const float* linb   = (const float*)d_in[10];
    float* outp = (float*)d_out;

    __half* pWhh; cudaGetSymbolAddress((void**)&pWhh, g_Whh);
    float* pO1;  cudaGetSymbolAddress((void**)&pO1,  g_out1);
    float* pO2;  cudaGetSymbolAddress((void**)&pO2,  g_out2);

    static int attr_done = 0;
    if (!attr_done) {
        cudaFuncSetAttribute(gemm_fused_kernel<FIN>,
                             cudaFuncAttributeMaxDynamicSharedMemorySize, GEMM_SMEM);
        cudaFuncSetAttribute(gemm_fused_kernel<HF>,
                             cudaFuncAttributeMaxDynamicSharedMemorySize, GEMM_SMEM);
        attr_done = 1;
    }

    dim3 g1(2, (NN + 127) / 128);
    int aggBlocks = (NN * 32 + 255) / 256;

    init_kernel<<<(GG * HF + 255) / 256, 256>>>();
    count_kernel<<<(EE + 255) / 256, 256>>>(ei);
    scan_kernel<<<1, 1024>>>();
    gemm_fused_kernel<FIN><<<g1, 256, GEMM_SMEM>>>(x, W1, pWhh, a1s, a1d, NN);  // profiled slot
    scatter_kernel<<<(EE + 255) / 256, 256>>>(ei);
    agg_kernel<<<aggBlocks, 256>>>(pWhh, pO1);

    gemm_fused_kernel<HF><<<g1, 256, GEMM_SMEM>>>(pO1, W2, pWhh, a2s, a2d, NN);
    agg_kernel<<<aggBlocks, 256>>>(pWhh, pO2);

    pool_kernel<<<(NN + PN - 1) / PN, 256>>>(pO2, batch);
    final_kernel<<<(GG * CC + 255) / 256, 256>>>(linW, linb, outp);
}

// round 12
// speedup vs baseline: 1.8921x; 1.3244x over previous
#include <cuda_runtime.h>
#include <cuda_fp16.h>
#include <math_constants.h>

#define NN 50000
#define EE 800000
#define FIN 128
#define HF 256      // HEADS*HID = 4*64
#define GG 256
#define CC 10

typedef unsigned long long ull;

// ---------------- scratch (no allocations allowed) ----------------
__device__ __half g_Whh[(size_t)NN * HF];   // Wh in fp16 (gather source)
__device__ float g_out1[(size_t)NN * HF];
__device__ float g_out2[(size_t)NN * HF];
__device__ float g_ls[NN * 4];
__device__ float g_ld[NN * 4];
__device__ int   g_deg[NN];
__device__ int   g_rowptr[NN + 1];
__device__ int   g_cursor[NN];
__device__ int   g_srcs[EE];
__device__ float g_mx[GG * HF];
__device__ float g_sm[GG * HF];
__device__ int   g_cnt[GG];

__device__ __forceinline__ unsigned f16x2_of(float lo, float hi) {
    unsigned r;
    asm("cvt.rn.f16x2.f32 %0, %1, %2;" : "=r"(r) : "f"(hi), "f"(lo));  // first src -> high half
    return r;
}
__device__ __forceinline__ float2 h2f(unsigned u) {
    __half2 h = *reinterpret_cast<__half2*>(&u);
    return __half22float2(h);
}
__device__ __forceinline__ unsigned tf32_of(float f) {
    unsigned r;
    asm("cvt.rna.tf32.f32 %0, %1;" : "=r"(r) : "f"(f));
    return r;
}
__device__ __forceinline__ void mma_tf32(float* c, const unsigned* a, const unsigned* b) {
    asm("mma.sync.aligned.m16n8k8.row.col.f32.tf32.tf32.f32 "
        "{%0,%1,%2,%3}, {%4,%5,%6,%7}, {%8,%9}, {%0,%1,%2,%3};"
        : "+f"(c[0]), "+f"(c[1]), "+f"(c[2]), "+f"(c[3])
        : "r"(a[0]), "r"(a[1]), "r"(a[2]), "r"(a[3]), "r"(b[0]), "r"(b[1]));
}
__device__ __forceinline__ void cp16(void* smem_dst, const void* gsrc) {
    unsigned s = (unsigned)__cvta_generic_to_shared(smem_dst);
    asm volatile("cp.async.cg.shared.global [%0], [%1], 16;" :: "r"(s), "l"(gsrc));
}
__device__ __forceinline__ void cp_commit() { asm volatile("cp.async.commit_group;"); }
__device__ __forceinline__ void cp_wait1() { asm volatile("cp.async.wait_group 1;"); }
__device__ __forceinline__ void cp_wait0() { asm volatile("cp.async.wait_group 0;"); }

// ---------------- init ----------------
__global__ void init_kernel() {
    int i = blockIdx.x * blockDim.x + threadIdx.x;
    if (i < NN) g_deg[i] = 0;
    if (i < GG * HF) { g_mx[i] = -CUDART_INF_F; g_sm[i] = 0.f; }
    if (i < GG) g_cnt[i] = 0;
}

// ---------------- CSR build ----------------
__global__ void count_kernel(const int* __restrict__ ei) {
    int e = blockIdx.x * blockDim.x + threadIdx.x;
    if (e >= EE) return;
    atomicAdd(&g_deg[ei[EE + e]], 1);
}

__global__ void scan_kernel() {
    const int T = 1024;
    int tid = threadIdx.x;
    int per = (NN + T - 1) / T;
    int start = tid * per;
    int end = start + per; if (end > NN) end = NN; if (start > NN) start = NN;
    int s = 0;
    for (int i = start; i < end; i++) s += g_deg[i];
    __shared__ int sums[T];
    sums[tid] = s;
    __syncthreads();
    for (int off = 1; off < T; off <<= 1) {
        int v = (tid >= off) ? sums[tid - off] : 0;
        __syncthreads();
        sums[tid] += v;
        __syncthreads();
    }
    int run = (tid > 0) ? sums[tid - 1] : 0;
    for (int i = start; i < end; i++) {
        g_rowptr[i] = run;
        g_cursor[i] = run;
        run += g_deg[i];
    }
    if (tid == T - 1) g_rowptr[NN] = run;
}

__global__ void scatter_kernel(const int* __restrict__ ei) {
    int e = blockIdx.x * blockDim.x + threadIdx.x;
    if (e >= EE) return;
    int dst = ei[EE + e];
    int pos = atomicAdd(&g_cursor[dst], 1);
    g_srcs[pos] = ei[e];
}

// ---- GEMM (tf32 tensor core) + fused logits: Whh[M,256] = fp16(A[M,K]*B[K,256]) ----
// 8 warps as 4(m)x2(n); warp tile 32x64 (one head per warp); cp.async double buffer.
#define LDA 36
#define LDB 136
#define GEMM_SMEM ((2 * 128 * LDA + 2 * 32 * LDB) * 4 + 2 * 128 * 4)
template <int K>
__global__ __launch_bounds__(256, 2)
void gemm_fused_kernel(const float* __restrict__ A, const float* __restrict__ B,
                       __half* __restrict__ Whh,
                       const float* __restrict__ a_src, const float* __restrict__ a_dst,
                       int M) {
    constexpr int BM = 128, BN = 128, BK = 32;
    constexpr int T = K / BK;
    extern __shared__ __align__(16) char smem_raw[];
    float* AsBase = (float*)smem_raw;                 // 2 x BM x LDA
    float* BsBase = AsBase + 2 * BM * LDA;            // 2 x BK x LDB
    float* s_as = BsBase + 2 * BK * LDB;
    float* s_ad = s_as + BN;

    int tid = threadIdx.x;
    int lane = tid & 31, w = tid >> 5;
    int wm = w >> 1, wn = w & 1;
    int g = lane >> 2, tig = lane & 3;
    int m0 = blockIdx.y * BM, n0 = blockIdx.x * BN;   // n0 in {0,128}
    if (tid < BN) { s_as[tid] = a_src[n0 + tid]; s_ad[tid] = a_dst[n0 + tid]; }

    float c[2][8][4];
#pragma unroll
    for (int tm = 0; tm < 2; tm++)
#pragma unroll
        for (int tn = 0; tn < 8; tn++)
#pragma unroll
            for (int j = 0; j < 4; j++) c[tm][tn][j] = 0.f;

    auto issue = [&](int st, int k0) {
        float* Ast = AsBase + st * BM * LDA;
        float* Bst = BsBase + st * BK * LDB;
#pragma unroll
        for (int u = 0; u < 4; u++) {
            int ch = tid + u * 256;                  // 0..1023
            int m = ch >> 3, kq = (ch & 7) * 4;      // A: 128 rows x 8 chunks
            int gm = m0 + m; if (gm >= M) gm = M - 1;
            cp16(Ast + m * LDA + kq, &A[(size_t)gm * K + k0 + kq]);
            int r = ch >> 5, cq = (ch & 31) * 4;     // B: 32 rows x 32 chunks
            cp16(Bst + r * LDB + cq, &B[(size_t)(k0 + r) * 256 + n0 + cq]);
        }
        cp_commit();
    };

    issue(0, 0);

#pragma unroll 1
    for (int t = 0; t < T; t++) {
        int st = t & 1;
        if (t + 1 < T) { issue(st ^ 1, (t + 1) * BK); cp_wait1(); }
        else           { cp_wait0(); }
        __syncthreads();
        float* Ast = AsBase + st * BM * LDA;
        float* Bst = BsBase + st * BK * LDB;
#pragma unroll
        for (int ks = 0; ks < BK / 8; ks++) {
            unsigned af[2][4], bf[8][2];
#pragma unroll
            for (int tm = 0; tm < 2; tm++) {
                int r0 = (wm * 32 + tm * 16 + g) * LDA + ks * 8 + tig;
                af[tm][0] = tf32_of(Ast[r0]);
                af[tm][1] = tf32_of(Ast[r0 + 8 * LDA]);
                af[tm][2] = tf32_of(Ast[r0 + 4]);
                af[tm][3] = tf32_of(Ast[r0 + 8 * LDA + 4]);
            }
#pragma unroll
            for (int tn = 0; tn < 8; tn++) {
                int nb = (ks * 8 + tig) * LDB + wn * 64 + tn * 8 + g;
                bf[tn][0] = tf32_of(Bst[nb]);
                bf[tn][1] = tf32_of(Bst[nb + 4 * LDB]);
            }
#pragma unroll
            for (int tm = 0; tm < 2; tm++)
#pragma unroll
                for (int tn = 0; tn < 8; tn++)
                    mma_tf32(c[tm][tn], af[tm], bf[tn]);
        }
        __syncthreads();
    }

    // ---- epilogue: fp16 Whh store + fused ls/ld ----
    int h = (n0 >> 6) + wn;   // head owned by this warp
#pragma unroll
    for (int tm = 0; tm < 2; tm++) {
        int rA = m0 + wm * 32 + tm * 16 + g;
        int rB = rA + 8;
        float lsA = 0.f, ldA = 0.f, lsB = 0.f, ldB = 0.f;
#pragma unroll
        for (int tn = 0; tn < 8; tn++) {
            int col = wn * 64 + tn * 8 + tig * 2;
            float c0 = c[tm][tn][0], c1 = c[tm][tn][1];
            float c2 = c[tm][tn][2], c3 = c[tm][tn][3];
            if (rA < M) *(unsigned*)&Whh[(size_t)rA * 256 + n0 + col] = f16x2_of(c0, c1);
            if (rB < M) *(unsigned*)&Whh[(size_t)rB * 256 + n0 + col] = f16x2_of(c2, c3);
            lsA += c0 * s_as[col] + c1 * s_as[col + 1];
            ldA += c0 * s_ad[col] + c1 * s_ad[col + 1];
            lsB += c2 * s_as[col] + c3 * s_as[col + 1];
            ldB += c2 * s_ad[col] + c3 * s_ad[col + 1];
        }
#pragma unroll
        for (int off = 1; off <= 2; off <<= 1) {
            lsA += __shfl_xor_sync(0xffffffffu, lsA, off);
            ldA += __shfl_xor_sync(0xffffffffu, ldA, off);
            lsB += __shfl_xor_sync(0xffffffffu, lsB, off);
            ldB += __shfl_xor_sync(0xffffffffu, ldB, off);
        }
        if (tig == 0) {
            if (rA < M) { g_ls[rA * 4 + h] = lsA; g_ld[rA * 4 + h] = ldA; }
            if (rB < M) { g_ls[rB * 4 + h] = lsB; g_ld[rB * 4 + h] = ldB; }
        }
    }
}

// ---- fused edge-softmax + aggregation + ELU (warp per dst) ----
__device__ __forceinline__ void acc_edge(float* acc, float ph, uint4 w) {
    float2 f0 = h2f(w.x), f1 = h2f(w.y), f2 = h2f(w.z), f3 = h2f(w.w);
    acc[0] = fmaf(ph, f0.x, acc[0]); acc[1] = fmaf(ph, f0.y, acc[1]);
    acc[2] = fmaf(ph, f1.x, acc[2]); acc[3] = fmaf(ph, f1.y, acc[3]);
    acc[4] = fmaf(ph, f2.x, acc[4]); acc[5] = fmaf(ph, f2.y, acc[5]);
    acc[6] = fmaf(ph, f3.x, acc[6]); acc[7] = fmaf(ph, f3.y, acc[7]);
}

__global__ __launch_bounds__(256)
void agg_kernel(const __half* __restrict__ Whh, float* __restrict__ out) {
    int warp = (blockIdx.x * blockDim.x + threadIdx.x) >> 5;
    int lane = threadIdx.x & 31;
    if (warp >= NN) return;
    int n = warp;
    int start = g_rowptr[n], end = g_rowptr[n + 1];
    int hsel = lane >> 3;
    float dnh = g_ld[n * 4 + hsel];

    float acc[8];
#pragma unroll
    for (int j = 0; j < 8; j++) acc[j] = 0.f;
    float zh = 0.f;

    int i = start;
    for (; i + 7 < end; i += 8) {
        int s[8];
#pragma unroll
        for (int u = 0; u < 8; u++) s[u] = g_srcs[i + u];
        uint4 w[8];
#pragma unroll
        for (int u = 0; u < 8; u++)
            w[u] = *(const uint4*)(Whh + (size_t)s[u] * HF + lane * 8);
        float e[8];
#pragma unroll
        for (int u = 0; u < 8; u++) e[u] = g_ls[s[u] * 4 + hsel] + dnh;
#pragma unroll
        for (int u = 0; u < 8; u++) {
            float p = __expf(fmaxf(e[u], 0.01f * e[u]));
            zh += p;
            acc_edge(acc, p, w[u]);
        }
    }
    for (; i + 3 < end; i += 4) {
        int s[4];
#pragma unroll
        for (int u = 0; u < 4; u++) s[u] = g_srcs[i + u];
        uint4 w[4];
#pragma unroll
        for (int u = 0; u < 4; u++)
            w[u] = *(const uint4*)(Whh + (size_t)s[u] * HF + lane * 8);
#pragma unroll
        for (int u = 0; u < 4; u++) {
            float e = g_ls[s[u] * 4 + hsel] + dnh;
            float p = __expf(fmaxf(e, 0.01f * e));
            zh += p;
            acc_edge(acc, p, w[u]);
        }
    }
    for (; i < end; i++) {
        int s = g_srcs[i];
        float e = g_ls[s * 4 + hsel] + dnh;
        uint4 w = *(const uint4*)(Whh + (size_t)s * HF + lane * 8);
        float p = __expf(fmaxf(e, 0.01f * e));
        zh += p;
        acc_edge(acc, p, w);
    }
    float inv = 1.f / (zh + 1e-16f);
    float res[8];
#pragma unroll
    for (int j = 0; j < 8; j++) {
        float v = acc[j] * inv;
        res[j] = v > 0.f ? v : (__expf(v) - 1.f);  // ELU
    }
    float* o = out + (size_t)n * HF + lane * 8;
    *(float4*)o = make_float4(res[0], res[1], res[2], res[3]);
    *(float4*)(o + 4) = make_float4(res[4], res[5], res[6], res[7]);
}

// ---------------- segmented pooling (batch is sorted) ----------------
#define PN 128
__device__ __forceinline__ void pool_flush(int g, int f, float mx, float sm) {
    if (mx > -CUDART_INF_F) {
        int* amx = (int*)&g_mx[g * HF + f];
        if (mx >= 0.f) atomicMax(amx, __float_as_int(mx));
        else atomicMin((unsigned int*)amx, (unsigned int)__float_as_int(mx));
        atomicAdd(&g_sm[g * HF + f], sm);
    }
}
__global__ __launch_bounds__(256)
void pool_kernel(const float* __restrict__ x, const int* __restrict__ batch) {
    __shared__ int sb[PN];
    int b0 = blockIdx.x * PN;
    int cnt = NN - b0; if (cnt > PN) cnt = PN;
    for (int i = threadIdx.x; i < cnt; i += 256) sb[i] = batch[b0 + i];
    __syncthreads();
    int f = threadIdx.x;
    int g = sb[0];
    float mx = -CUDART_INF_F, sm = 0.f;
    int segc = 0;
    for (int i = 0; i < cnt; i++) {
        int gb = sb[i];
        if (gb != g) {
            pool_flush(g, f, mx, sm);
            if (f == 0) atomicAdd(&g_cnt[g], segc);
            g = gb; mx = -CUDART_INF_F; sm = 0.f; segc = 0;
        }
        float v = x[(size_t)(b0 + i) * HF + f];
        mx = fmaxf(mx, v); sm += v; segc++;
    }
    pool_flush(g, f, mx, sm);
    if (f == 0) atomicAdd(&g_cnt[g], segc);
}

// ---------------- finalize pool + linear ----------------
__global__ void final_kernel(const float* __restrict__ linW, const float* __restrict__ linb,
                             float* __restrict__ outp) {
    int t = blockIdx.x * blockDim.x + threadIdx.x;
    if (t >= GG * CC) return;
    int g = t / CC, c = t % CC;
    float cnt = fmaxf((float)g_cnt[g], 1.f);
    float inv = 1.f / cnt;
    float acc = linb[c];
    const float* mxr = g_mx + g * HF;
    const float* smr = g_sm + g * HF;
#pragma unroll 4
    for (int f = 0; f < HF; f++) {
        float mv = mxr[f];
        if (!isfinite(mv)) mv = 0.f;
        acc = fmaf(mv, linW[f * CC + c], acc);
    }
#pragma unroll 4
    for (int f = 0; f < HF; f++) {
        acc = fmaf(smr[f] * inv, linW[(HF + f) * CC + c], acc);
    }
    outp[t] = acc;
}

// ---------------- launch ----------------
extern "C" void kernel_launch(void* const* d_in, const int* in_sizes, int n_in,
                              void* d_out, int out_size) {
    const float* x      = (const float*)d_in[0];
    const int*   ei     = (const int*)d_in[1];
    const int*   batch  = (const int*)d_in[2];
    const float* W1     = (const float*)d_in[3];
    const float* a1s    = (const float*)d_in[4];
    const float* a1d    = (const float*)d_in[5];
    const float* W2     = (const float*)d_in[6];
    const float* a2s    = (const float*)d_in[7];
    const float* a2d    = (const float*)d_in[8];
    const float* linW   = (const float*)d_in[9];
    const float* linb   = (const float*)d_in[10];
    float* outp = (float*)d_out;

    __half* pWhh; cudaGetSymbolAddress((void**)&pWhh, g_Whh);
    float* pO1;  cudaGetSymbolAddress((void**)&pO1,  g_out1);
    float* pO2;  cudaGetSymbolAddress((void**)&pO2,  g_out2);

    static int attr_done = 0;
    if (!attr_done) {
        cudaFuncSetAttribute(gemm_fused_kernel<FIN>,
                             cudaFuncAttributeMaxDynamicSharedMemorySize, GEMM_SMEM);
        cudaFuncSetAttribute(gemm_fused_kernel<HF>,
                             cudaFuncAttributeMaxDynamicSharedMemorySize, GEMM_SMEM);
        attr_done = 1;
    }

    dim3 g1(2, (NN + 127) / 128);
    int aggBlocks = (NN * 32 + 255) / 256;

    init_kernel<<<(GG * HF + 255) / 256, 256>>>();
    count_kernel<<<(EE + 255) / 256, 256>>>(ei);
    scan_kernel<<<1, 1024>>>();
    gemm_fused_kernel<FIN><<<g1, 256, GEMM_SMEM>>>(x, W1, pWhh, a1s, a1d, NN);  // profiled slot
    scatter_kernel<<<(EE + 255) / 256, 256>>>(ei);
    agg_kernel<<<aggBlocks, 256>>>(pWhh, pO1);

    gemm_fused_kernel<HF><<<g1, 256, GEMM_SMEM>>>(pO1, W2, pWhh, a2s, a2d, NN);
    agg_kernel<<<aggBlocks, 256>>>(pWhh, pO2);

    pool_kernel<<<(NN + PN - 1) / PN, 256>>>(pO2, batch);
    final_kernel<<<(GG * CC + 255) / 256, 256>>>(linW, linb, outp);
}